// round 2
// baseline (speedup 1.0000x reference)
#include <cuda_runtime.h>
#include <math.h>

#define NN 50000
#define NE 1200000
#define NG 128
#define EPSF 1e-7f
#define MAXNORM (1.0f - 1e-5f)
#define ACLAMP 6.1030338f   // arctanh(1 - 1e-5)

// ---------------- scratch (static device globals; no allocation) -------------
__device__ int   g_flagE;          // 1 => edge_index is int64
__device__ int   g_flagB;          // 1 => batch is int64
__device__ int   g_deg[NN];
__device__ int   g_off[NN];
__device__ int   g_cur[NN];
__device__ int   g_adj[NE];
__device__ int   g_gcnt[NG];
__device__ float g_pool[NG * 64];
__device__ float g_ta[NN * 64];
__device__ float g_tb[NN * 64];
__device__ float g_agg[NN * 64];

// ---------------- utility kernels -------------------------------------------
__global__ void zero_kernel() {
    int i = blockIdx.x * blockDim.x + threadIdx.x;
    if (i < NN)      g_deg[i]  = 0;
    if (i < NG)      g_gcnt[i] = 0;
    if (i < NG * 64) g_pool[i] = 0.0f;
}

// Detect int64 vs int32 by checking whether all odd 32-bit words in a window
// are zero (int64 hi-halves of values < 2^31 are always 0). Windows are taken
// mid-array so the sorted batch head (all zeros for graph 0) can't fool it.
__global__ void detect_kernel(const int* __restrict__ ei, const int* __restrict__ ba) {
    __shared__ int nzE, nzB;
    if (threadIdx.x == 0) { nzE = 0; nzB = 0; }
    __syncthreads();
    for (int w = NE + 1 + 2 * threadIdx.x; w < NE + 2048; w += 2 * blockDim.x)
        if (ei[w] != 0) atomicOr(&nzE, 1);
    for (int w = 48001 + 2 * threadIdx.x; w < 50000; w += 2 * blockDim.x)
        if (ba[w] != 0) atomicOr(&nzB, 1);
    __syncthreads();
    if (threadIdx.x == 0) { g_flagE = (nzE == 0); g_flagB = (nzB == 0); }
}

__device__ __forceinline__ int load_idx(const void* p, int i, int flag64) {
    return flag64 ? (int)((const long long*)p)[i] : ((const int*)p)[i];
}

__global__ void deg_kernel(const void* __restrict__ ei) {
    int e = blockIdx.x * blockDim.x + threadIdx.x;
    if (e >= NE) return;
    int dst = load_idx(ei, NE + e, g_flagE);
    atomicAdd(&g_deg[dst], 1);
}

__global__ void gcnt_kernel(const void* __restrict__ ba) {
    __shared__ int h[NG];
    for (int i = threadIdx.x; i < NG; i += blockDim.x) h[i] = 0;
    __syncthreads();
    int f = g_flagB;
    for (int n = blockIdx.x * blockDim.x + threadIdx.x; n < NN; n += gridDim.x * blockDim.x) {
        int g = load_idx(ba, n, f);
        atomicAdd(&h[g], 1);
    }
    __syncthreads();
    for (int i = threadIdx.x; i < NG; i += blockDim.x)
        if (h[i]) atomicAdd(&g_gcnt[i], h[i]);
}

// Single-block exclusive scan of g_deg -> g_off (and g_cur copy).
__global__ void scan_kernel() {
    __shared__ int sh[1024];
    int tid = threadIdx.x;
    int running = 0;
    for (int base = 0; base < NN; base += 1024) {
        int v = (base + tid < NN) ? g_deg[base + tid] : 0;
        sh[tid] = v;
        __syncthreads();
        for (int off = 1; off < 1024; off <<= 1) {
            int t = (tid >= off) ? sh[tid - off] : 0;
            __syncthreads();
            sh[tid] += t;
            __syncthreads();
        }
        if (base + tid < NN) {
            int excl = running + sh[tid] - v;
            g_off[base + tid] = excl;
            g_cur[base + tid] = excl;
        }
        running += sh[1023];
        __syncthreads();
    }
}

__global__ void adj_kernel(const void* __restrict__ ei) {
    int e = blockIdx.x * blockDim.x + threadIdx.x;
    if (e >= NE) return;
    int f = g_flagE;
    int src = load_idx(ei, e, f);
    int dst = load_idx(ei, NE + e, f);
    int pos = atomicAdd(&g_cur[dst], 1);
    g_adj[pos] = src;
}

// t0 = norm-clamp(x) in tangent space (32-d), one warp per node
__global__ void t0_kernel(const float* __restrict__ x) {
    int gid = blockIdx.x * blockDim.x + threadIdx.x;
    int node = gid >> 5, lane = gid & 31;
    if (node >= NN) return;
    float v = x[node * 32 + lane];
    float ss = v * v;
    #pragma unroll
    for (int o = 16; o; o >>= 1) ss += __shfl_xor_sync(0xffffffffu, ss, o);
    float nrm = sqrtf(ss);
    float s = (nrm > ACLAMP) ? (ACLAMP / nrm) : 1.0f;
    g_ta[node * 32 + lane] = v * s;
}

// ---------------- aggregation: mean over in-edges (warp per node) ------------
template <int DIM, int SRC>
__global__ void agg_kernel() {
    const float* __restrict__ tin = SRC ? g_tb : g_ta;
    int gid = blockIdx.x * blockDim.x + threadIdx.x;
    int node = gid >> 5, lane = gid & 31;
    if (node >= NN) return;
    int o = g_off[node];
    int d = g_deg[node];
    float a0 = 0.0f, a1 = 0.0f, b0 = 0.0f, b1 = 0.0f;
    int j = 0;
    for (; j + 4 <= d; j += 4) {
        int s0 = g_adj[o + j], s1 = g_adj[o + j + 1];
        int s2 = g_adj[o + j + 2], s3 = g_adj[o + j + 3];
        float v0 = tin[s0 * DIM + lane], v1 = tin[s1 * DIM + lane];
        float v2 = tin[s2 * DIM + lane], v3 = tin[s3 * DIM + lane];
        a0 += v0 + v1;
        b0 += v2 + v3;
        if (DIM == 64) {
            float u0 = tin[s0 * DIM + 32 + lane], u1 = tin[s1 * DIM + 32 + lane];
            float u2 = tin[s2 * DIM + 32 + lane], u3 = tin[s3 * DIM + 32 + lane];
            a1 += u0 + u1;
            b1 += u2 + u3;
        }
    }
    for (; j < d; j++) {
        int s = g_adj[o + j];
        a0 += tin[s * DIM + lane];
        if (DIM == 64) a1 += tin[s * DIM + 32 + lane];
    }
    float inv = 1.0f / (float)((d > 0) ? d : 1);
    g_agg[node * DIM + lane] = (a0 + b0) * inv;
    if (DIM == 64) g_agg[node * DIM + 32 + lane] = (a1 + b1) * inv;
}

// ---------- GEMM (agg @ W + b) + act + norm-clamp + deg==0 zeroing -----------
// Block: 256 threads, tile 64 nodes x 64 outputs, 4x4 micro-tile per thread.
template <int DIMIN, int ACT, int DSTB>
__global__ __launch_bounds__(256) void gemm_kernel(const float* __restrict__ W,
                                                   const float* __restrict__ b) {
    float* __restrict__ tout = DSTB ? g_tb : g_ta;
    __shared__ float As[64 * 65];                  // reused as output staging
    __shared__ __align__(16) float Ws[64 * 64];
    __shared__ float ssc[64];
    int tid = threadIdx.x;
    int row0 = blockIdx.x * 64;

    for (int idx = tid; idx < 64 * DIMIN; idx += 256) {
        int r = idx / DIMIN, c = idx % DIMIN;
        int row = row0 + r;
        As[r * 65 + c] = (row < NN) ? g_agg[row * DIMIN + c] : 0.0f;
    }
    for (int idx = tid; idx < DIMIN * 64; idx += 256) Ws[idx] = W[idx];
    __syncthreads();

    int rb = (tid >> 4) * 4, cb = (tid & 15) * 4;
    float acc[4][4];
    #pragma unroll
    for (int i = 0; i < 4; i++)
        #pragma unroll
        for (int j = 0; j < 4; j++) acc[i][j] = b[cb + j];

    #pragma unroll 8
    for (int k = 0; k < DIMIN; k++) {
        float a0 = As[(rb + 0) * 65 + k];
        float a1 = As[(rb + 1) * 65 + k];
        float a2 = As[(rb + 2) * 65 + k];
        float a3 = As[(rb + 3) * 65 + k];
        float4 w = *(const float4*)&Ws[k * 64 + cb];
        acc[0][0] += a0 * w.x; acc[0][1] += a0 * w.y; acc[0][2] += a0 * w.z; acc[0][3] += a0 * w.w;
        acc[1][0] += a1 * w.x; acc[1][1] += a1 * w.y; acc[1][2] += a1 * w.z; acc[1][3] += a1 * w.w;
        acc[2][0] += a2 * w.x; acc[2][1] += a2 * w.y; acc[2][2] += a2 * w.z; acc[2][3] += a2 * w.w;
        acc[3][0] += a3 * w.x; acc[3][1] += a3 * w.y; acc[3][2] += a3 * w.z; acc[3][3] += a3 * w.w;
    }
    __syncthreads();   // As reads done; reuse as output staging

    #pragma unroll
    for (int i = 0; i < 4; i++)
        #pragma unroll
        for (int j = 0; j < 4; j++) {
            float u = acc[i][j];
            if (ACT) u = (u > 0.0f) ? u : 0.2f * u;   // leaky_relu 0.2
            As[(rb + i) * 65 + (cb + j)] = u;
        }
    __syncthreads();

    if (tid < 64) {
        float ss = 0.0f;
        #pragma unroll 8
        for (int c = 0; c < 64; c++) { float u = As[tid * 65 + c]; ss += u * u; }
        float nrm = sqrtf(ss);
        float s = (nrm > ACLAMP) ? (ACLAMP / nrm) : 1.0f;
        int row = row0 + tid;
        if (row < NN && g_deg[row] == 0) s = 0.0f;   // empty mean -> 0, no bias
        ssc[tid] = s;
    }
    __syncthreads();

    for (int idx = tid; idx < 64 * 64; idx += 256) {
        int r = idx >> 6, c = idx & 63;
        int row = row0 + r;
        if (row < NN) tout[row * 64 + c] = As[r * 65 + c] * ssc[r];
    }
}

// ---------------- graph pooling (batch is sorted -> run-length accumulate) ---
__global__ void pool_kernel(const void* __restrict__ ba) {
    const float* __restrict__ t3 = g_tb;   // layer 3 output
    int c = threadIdx.x;                   // 0..63
    int n0 = blockIdx.x * 128;
    int n1 = min(n0 + 128, NN);
    if (n0 >= NN) return;
    int f = g_flagB;
    int gprev = load_idx(ba, n0, f);
    float acc = 0.0f;
    for (int n = n0; n < n1; n++) {
        int g = load_idx(ba, n, f);
        if (g != gprev) {
            atomicAdd(&g_pool[gprev * 64 + c], acc);
            acc = 0.0f;
            gprev = g;
        }
        acc += t3[n * 64 + c];
    }
    atomicAdd(&g_pool[gprev * 64 + c], acc);
}

// ---------------- head: mean-pool -> clamp -> linear -> expmap0 -> proj ------
__global__ void final_kernel(const float* __restrict__ Wl,
                             const float* __restrict__ bl,
                             float* __restrict__ out) {
    __shared__ float sht[64];
    __shared__ float shz[10];
    __shared__ float shred[2];
    __shared__ float shF;
    int g = blockIdx.x, c = threadIdx.x;
    float cnt = (float)max(g_gcnt[g], 1);
    float v = g_pool[g * 64 + c] / cnt;
    float ss = v * v;
    #pragma unroll
    for (int o = 16; o; o >>= 1) ss += __shfl_xor_sync(0xffffffffu, ss, o);
    if ((c & 31) == 0) shred[c >> 5] = ss;
    __syncthreads();
    float nrm = sqrtf(shred[0] + shred[1]);
    float s = (nrm > ACLAMP) ? (ACLAMP / nrm) : 1.0f;
    sht[c] = v * s;
    __syncthreads();
    if (c < 10) {
        float z = bl[c];
        #pragma unroll 8
        for (int k = 0; k < 64; k++) z += sht[k] * Wl[k * 10 + c];
        shz[c] = z;
    }
    __syncthreads();
    if (c == 0) {
        float s2 = 0.0f;
        #pragma unroll
        for (int j = 0; j < 10; j++) s2 += shz[j] * shz[j];
        float n2 = sqrtf(s2);
        float nn = fmaxf(n2, EPSF);
        float fac = tanhf(nn) / nn;          // expmap0 scale
        float ny = fac * n2;                 // |y|
        float F = fac;
        if (ny > MAXNORM) F = fac * (MAXNORM / fmaxf(ny, EPSF));   // proj
        shF = F;
    }
    __syncthreads();
    if (c < 10) out[g * 10 + c] = shz[c] * shF;
}

// ---------------- launch ------------------------------------------------------
extern "C" void kernel_launch(void* const* d_in, const int* in_sizes, int n_in,
                              void* d_out, int out_size) {
    const float* x  = (const float*)d_in[0];
    const void*  ei = d_in[1];
    const void*  ba = d_in[2];
    const float* W1 = (const float*)d_in[3];
    const float* b1 = (const float*)d_in[4];
    const float* W2 = (const float*)d_in[5];
    const float* b2 = (const float*)d_in[6];
    const float* W3 = (const float*)d_in[7];
    const float* b3 = (const float*)d_in[8];
    const float* Wl = (const float*)d_in[9];
    const float* bl = (const float*)d_in[10];
    float* out = (float*)d_out;

    zero_kernel<<<(NN + 255) / 256, 256>>>();
    detect_kernel<<<1, 256>>>((const int*)ei, (const int*)ba);
    deg_kernel<<<(NE + 255) / 256, 256>>>(ei);
    gcnt_kernel<<<128, 256>>>(ba);
    scan_kernel<<<1, 1024>>>();
    adj_kernel<<<(NE + 255) / 256, 256>>>(ei);

    t0_kernel<<<(NN * 32 + 255) / 256, 256>>>(x);

    const int WARPS_GRID = (NN * 32 + 255) / 256;   // warp per node
    const int GEMM_GRID  = (NN + 63) / 64;

    // layer 1: agg(t0 in g_ta, 32d) -> gemm W1 (+lrelu) -> g_tb
    agg_kernel<32, 0><<<WARPS_GRID, 256>>>();
    gemm_kernel<32, 1, 1><<<GEMM_GRID, 256>>>(W1, b1);
    // layer 2: agg(g_tb, 64d) -> gemm W2 (+lrelu) -> g_ta
    agg_kernel<64, 1><<<WARPS_GRID, 256>>>();
    gemm_kernel<64, 1, 0><<<GEMM_GRID, 256>>>(W2, b2);
    // layer 3: agg(g_ta, 64d) -> gemm W3 (no act) -> g_tb
    agg_kernel<64, 0><<<WARPS_GRID, 256>>>();
    gemm_kernel<64, 0, 1><<<GEMM_GRID, 256>>>(W3, b3);

    pool_kernel<<<(NN + 127) / 128, 64>>>(ba);
    final_kernel<<<NG, 64>>>(Wl, bl, out);
}

// round 3
// speedup vs baseline: 1.3257x; 1.3257x over previous
#include <cuda_runtime.h>
#include <cuda_fp16.h>
#include <math.h>

#define NN 50000
#define NE 1200000
#define NG 128
#define NBLK 49            // ceil(NN/1024)
#define EPSF 1e-7f
#define MAXNORM (1.0f - 1e-5f)
#define ACLAMP 6.1030338f  // arctanh(1 - 1e-5)

// ---------------- scratch (static device globals; no allocation) -------------
__device__ int     g_flagE;
__device__ int     g_flagB;
__device__ int     g_deg[NN];
__device__ int     g_off[NN];
__device__ int     g_cur[NN];
__device__ int     g_adj[NE];
__device__ int     g_bsum[64];
__device__ int     g_bbase[64];
__device__ int     g_gcnt[NG];
__device__ float   g_pool[NG * 64];
__device__ __half2 g_th2[NN * 32];   // node features, fp16 (stride 32 or 64 halves)
__device__ float   g_agg[NN * 64];

#define G_TH ((__half*)g_th2)

// ---------------- utility kernels -------------------------------------------
__global__ void zero_kernel() {
    int i = blockIdx.x * blockDim.x + threadIdx.x;
    if (i < NN)      g_deg[i]  = 0;
    if (i < NG * 64) g_pool[i] = 0.0f;
}

// int64-vs-int32 sniffer: odd 32-bit words of small int64 values are all zero.
__global__ void detect_kernel(const int* __restrict__ ei, const int* __restrict__ ba) {
    __shared__ int nzE, nzB;
    if (threadIdx.x == 0) { nzE = 0; nzB = 0; }
    __syncthreads();
    for (int w = NE + 1 + 2 * threadIdx.x; w < NE + 2048; w += 2 * blockDim.x)
        if (ei[w] != 0) atomicOr(&nzE, 1);
    for (int w = 48001 + 2 * threadIdx.x; w < 50000; w += 2 * blockDim.x)
        if (ba[w] != 0) atomicOr(&nzB, 1);
    __syncthreads();
    if (threadIdx.x == 0) { g_flagE = (nzE == 0); g_flagB = (nzB == 0); }
}

__device__ __forceinline__ int load_idx(const void* p, int i, int flag64) {
    return flag64 ? (int)((const long long*)p)[i] : ((const int*)p)[i];
}

__global__ void deg_kernel(const void* __restrict__ ei) {
    int e = blockIdx.x * blockDim.x + threadIdx.x;
    if (e >= NE) return;
    int dst = load_idx(ei, NE + e, g_flagE);
    atomicAdd(&g_deg[dst], 1);
}

// graph sizes via binary search on sorted batch (no atomics)
__global__ void gcnt_kernel(const void* __restrict__ ba) {
    int g = threadIdx.x;          // 0..127
    int f = g_flagB;
    int lo = 0, hi = NN;
    while (lo < hi) { int m = (lo + hi) >> 1; if (load_idx(ba, m, f) < g) lo = m + 1; else hi = m; }
    int l = lo;
    lo = 0; hi = NN;
    while (lo < hi) { int m = (lo + hi) >> 1; if (load_idx(ba, m, f) < g + 1) lo = m + 1; else hi = m; }
    g_gcnt[g] = lo - l;
}

// ---- 3-phase exclusive scan of g_deg -> g_off/g_cur -------------------------
__global__ void scan1_kernel() {   // 49 blocks x 1024: per-block inclusive scan
    int i = blockIdx.x * 1024 + threadIdx.x;
    int lane = threadIdx.x & 31, wid = threadIdx.x >> 5;
    int v = (i < NN) ? g_deg[i] : 0;
    int s = v;
    #pragma unroll
    for (int o = 1; o < 32; o <<= 1) { int t = __shfl_up_sync(0xffffffffu, s, o); if (lane >= o) s += t; }
    __shared__ int wsum[32];
    if (lane == 31) wsum[wid] = s;
    __syncthreads();
    if (wid == 0) {
        int t = wsum[lane];
        #pragma unroll
        for (int o = 1; o < 32; o <<= 1) { int u = __shfl_up_sync(0xffffffffu, t, o); if (lane >= o) t += u; }
        wsum[lane] = t;
    }
    __syncthreads();
    int incl = s + (wid ? wsum[wid - 1] : 0);
    if (i < NN) g_off[i] = incl;
    if (threadIdx.x == 1023) g_bsum[blockIdx.x] = incl;
}

__global__ void scan2_kernel() {   // scan the 49 block totals
    __shared__ int sh[64];
    int t = threadIdx.x;
    int v = (t < NBLK) ? g_bsum[t] : 0;
    sh[t] = v;
    __syncthreads();
    for (int o = 1; o < 64; o <<= 1) {
        int u = (t >= o) ? sh[t - o] : 0;
        __syncthreads();
        sh[t] += u;
        __syncthreads();
    }
    g_bbase[t] = sh[t] - v;        // exclusive
}

__global__ void scan3_kernel() {   // to exclusive + add block base
    int i = blockIdx.x * blockDim.x + threadIdx.x;
    if (i >= NN) return;
    int e = g_off[i] - g_deg[i] + g_bbase[i >> 10];
    g_off[i] = e;
    g_cur[i] = e;
}

__global__ void adj_kernel(const void* __restrict__ ei) {
    int e = blockIdx.x * blockDim.x + threadIdx.x;
    if (e >= NE) return;
    int f = g_flagE;
    int src = load_idx(ei, e, f);
    int dst = load_idx(ei, NE + e, f);
    int pos = atomicAdd(&g_cur[dst], 1);
    g_adj[pos] = src;
}

// t0 = norm-clamp(x), stored fp16 stride 32
__global__ void t0_kernel(const float* __restrict__ x) {
    int gid = blockIdx.x * blockDim.x + threadIdx.x;
    int node = gid >> 5, lane = gid & 31;
    if (node >= NN) return;
    float v = x[node * 32 + lane];
    float ss = v * v;
    #pragma unroll
    for (int o = 16; o; o >>= 1) ss += __shfl_xor_sync(0xffffffffu, ss, o);
    float nrm = sqrtf(ss);
    float s = (nrm > ACLAMP) ? (ACLAMP / nrm) : 1.0f;
    G_TH[node * 32 + lane] = __float2half_rn(v * s);
}

// ---------------- mean aggregation over in-edges (warp per node, fp16 in) ----
template <int DIM>
__global__ void agg_kernel() {
    int gid = blockIdx.x * blockDim.x + threadIdx.x;
    int node = gid >> 5, lane = gid & 31;
    if (node >= NN) return;
    int o = g_off[node];
    int d = g_deg[node];
    float inv = 1.0f / (float)((d > 0) ? d : 1);
    if (DIM == 32) {
        const __half* __restrict__ tin = G_TH;
        float a = 0.0f, b = 0.0f;
        int j = 0;
        for (; j + 4 <= d; j += 4) {
            int s0 = g_adj[o + j], s1 = g_adj[o + j + 1];
            int s2 = g_adj[o + j + 2], s3 = g_adj[o + j + 3];
            a += __half2float(tin[s0 * 32 + lane]) + __half2float(tin[s1 * 32 + lane]);
            b += __half2float(tin[s2 * 32 + lane]) + __half2float(tin[s3 * 32 + lane]);
        }
        for (; j < d; j++) a += __half2float(tin[g_adj[o + j] * 32 + lane]);
        g_agg[node * 32 + lane] = (a + b) * inv;
    } else {
        const __half2* __restrict__ tin = g_th2;   // 32 half2 per node (64 dims)
        float ax = 0.0f, ay = 0.0f, bx = 0.0f, by = 0.0f;
        int j = 0;
        for (; j + 4 <= d; j += 4) {
            int s0 = g_adj[o + j], s1 = g_adj[o + j + 1];
            int s2 = g_adj[o + j + 2], s3 = g_adj[o + j + 3];
            float2 v0 = __half22float2(tin[s0 * 32 + lane]);
            float2 v1 = __half22float2(tin[s1 * 32 + lane]);
            float2 v2 = __half22float2(tin[s2 * 32 + lane]);
            float2 v3 = __half22float2(tin[s3 * 32 + lane]);
            ax += v0.x + v1.x; ay += v0.y + v1.y;
            bx += v2.x + v3.x; by += v2.y + v3.y;
        }
        for (; j < d; j++) {
            float2 v = __half22float2(tin[g_adj[o + j] * 32 + lane]);
            ax += v.x; ay += v.y;
        }
        float2 r;
        r.x = (ax + bx) * inv;
        r.y = (ay + by) * inv;
        ((float2*)g_agg)[node * 32 + lane] = r;
    }
}

// ---------- GEMM (agg @ W + b) + act + norm-clamp + deg==0 zeroing -----------
template <int DIMIN, int ACT>
__global__ __launch_bounds__(256) void gemm_kernel(const float* __restrict__ W,
                                                   const float* __restrict__ b) {
    __shared__ float As[64 * 65];
    __shared__ __align__(16) float Ws[64 * 64];
    __shared__ float ssc[64];
    int tid = threadIdx.x;
    int row0 = blockIdx.x * 64;

    for (int idx = tid; idx < 64 * DIMIN; idx += 256) {
        int r = idx / DIMIN, c = idx % DIMIN;
        int row = row0 + r;
        As[r * 65 + c] = (row < NN) ? g_agg[row * DIMIN + c] : 0.0f;
    }
    for (int idx = tid; idx < DIMIN * 64; idx += 256) Ws[idx] = W[idx];
    __syncthreads();

    int rb = (tid >> 4) * 4, cb = (tid & 15) * 4;
    float acc[4][4];
    #pragma unroll
    for (int i = 0; i < 4; i++)
        #pragma unroll
        for (int j = 0; j < 4; j++) acc[i][j] = b[cb + j];

    #pragma unroll 8
    for (int k = 0; k < DIMIN; k++) {
        float a0 = As[(rb + 0) * 65 + k];
        float a1 = As[(rb + 1) * 65 + k];
        float a2 = As[(rb + 2) * 65 + k];
        float a3 = As[(rb + 3) * 65 + k];
        float4 w = *(const float4*)&Ws[k * 64 + cb];
        acc[0][0] += a0 * w.x; acc[0][1] += a0 * w.y; acc[0][2] += a0 * w.z; acc[0][3] += a0 * w.w;
        acc[1][0] += a1 * w.x; acc[1][1] += a1 * w.y; acc[1][2] += a1 * w.z; acc[1][3] += a1 * w.w;
        acc[2][0] += a2 * w.x; acc[2][1] += a2 * w.y; acc[2][2] += a2 * w.z; acc[2][3] += a2 * w.w;
        acc[3][0] += a3 * w.x; acc[3][1] += a3 * w.y; acc[3][2] += a3 * w.z; acc[3][3] += a3 * w.w;
    }
    __syncthreads();

    #pragma unroll
    for (int i = 0; i < 4; i++)
        #pragma unroll
        for (int j = 0; j < 4; j++) {
            float u = acc[i][j];
            if (ACT) u = (u > 0.0f) ? u : 0.2f * u;
            As[(rb + i) * 65 + (cb + j)] = u;
        }
    __syncthreads();

    if (tid < 64) {
        float ss = 0.0f;
        #pragma unroll 8
        for (int c = 0; c < 64; c++) { float u = As[tid * 65 + c]; ss += u * u; }
        float nrm = sqrtf(ss);
        float s = (nrm > ACLAMP) ? (ACLAMP / nrm) : 1.0f;
        int row = row0 + tid;
        if (row < NN && g_deg[row] == 0) s = 0.0f;
        ssc[tid] = s;
    }
    __syncthreads();

    for (int idx = tid; idx < 64 * 64; idx += 256) {
        int r = idx >> 6, c = idx & 63;
        int row = row0 + r;
        if (row < NN) G_TH[row * 64 + c] = __float2half_rn(As[r * 65 + c] * ssc[r]);
    }
}

// ---------------- graph pooling (batch sorted -> run-length accumulate) ------
__global__ void pool_kernel(const void* __restrict__ ba) {
    int c = threadIdx.x;               // 0..63
    int n0 = blockIdx.x * 128;
    int n1 = min(n0 + 128, NN);
    if (n0 >= NN) return;
    int f = g_flagB;
    int gprev = load_idx(ba, n0, f);
    float acc = 0.0f;
    for (int n = n0; n < n1; n++) {
        int g = load_idx(ba, n, f);
        if (g != gprev) {
            atomicAdd(&g_pool[gprev * 64 + c], acc);
            acc = 0.0f;
            gprev = g;
        }
        acc += __half2float(G_TH[n * 64 + c]);
    }
    atomicAdd(&g_pool[gprev * 64 + c], acc);
}

// ---------------- head: mean-pool -> clamp -> linear -> expmap0 -> proj ------
__global__ void final_kernel(const float* __restrict__ Wl,
                             const float* __restrict__ bl,
                             float* __restrict__ out) {
    __shared__ float sht[64];
    __shared__ float shz[10];
    __shared__ float shred[2];
    __shared__ float shF;
    int g = blockIdx.x, c = threadIdx.x;
    float cnt = (float)max(g_gcnt[g], 1);
    float v = g_pool[g * 64 + c] / cnt;
    float ss = v * v;
    #pragma unroll
    for (int o = 16; o; o >>= 1) ss += __shfl_xor_sync(0xffffffffu, ss, o);
    if ((c & 31) == 0) shred[c >> 5] = ss;
    __syncthreads();
    float nrm = sqrtf(shred[0] + shred[1]);
    float s = (nrm > ACLAMP) ? (ACLAMP / nrm) : 1.0f;
    sht[c] = v * s;
    __syncthreads();
    if (c < 10) {
        float z = bl[c];
        #pragma unroll 8
        for (int k = 0; k < 64; k++) z += sht[k] * Wl[k * 10 + c];
        shz[c] = z;
    }
    __syncthreads();
    if (c == 0) {
        float s2 = 0.0f;
        #pragma unroll
        for (int j = 0; j < 10; j++) s2 += shz[j] * shz[j];
        float n2 = sqrtf(s2);
        float nn = fmaxf(n2, EPSF);
        float fac = tanhf(nn) / nn;
        float ny = fac * n2;
        float F = fac;
        if (ny > MAXNORM) F = fac * (MAXNORM / fmaxf(ny, EPSF));
        shF = F;
    }
    __syncthreads();
    if (c < 10) out[g * 10 + c] = shz[c] * shF;
}

// ---------------- launch ------------------------------------------------------
extern "C" void kernel_launch(void* const* d_in, const int* in_sizes, int n_in,
                              void* d_out, int out_size) {
    const float* x  = (const float*)d_in[0];
    const void*  ei = d_in[1];
    const void*  ba = d_in[2];
    const float* W1 = (const float*)d_in[3];
    const float* b1 = (const float*)d_in[4];
    const float* W2 = (const float*)d_in[5];
    const float* b2 = (const float*)d_in[6];
    const float* W3 = (const float*)d_in[7];
    const float* b3 = (const float*)d_in[8];
    const float* Wl = (const float*)d_in[9];
    const float* bl = (const float*)d_in[10];
    float* out = (float*)d_out;

    zero_kernel<<<(NN + 255) / 256, 256>>>();
    detect_kernel<<<1, 256>>>((const int*)ei, (const int*)ba);
    deg_kernel<<<(NE + 255) / 256, 256>>>(ei);
    gcnt_kernel<<<1, 128>>>(ba);
    scan1_kernel<<<NBLK, 1024>>>();
    scan2_kernel<<<1, 64>>>();
    scan3_kernel<<<(NN + 255) / 256, 256>>>();
    adj_kernel<<<(NE + 255) / 256, 256>>>(ei);

    t0_kernel<<<(NN * 32 + 255) / 256, 256>>>(x);

    const int WARPS_GRID = (NN * 32 + 255) / 256;
    const int GEMM_GRID  = (NN + 63) / 64;

    agg_kernel<32><<<WARPS_GRID, 256>>>();
    gemm_kernel<32, 1><<<GEMM_GRID, 256>>>(W1, b1);
    agg_kernel<64><<<WARPS_GRID, 256>>>();
    gemm_kernel<64, 1><<<GEMM_GRID, 256>>>(W2, b2);
    agg_kernel<64><<<WARPS_GRID, 256>>>();
    gemm_kernel<64, 0><<<GEMM_GRID, 256>>>(W3, b3);

    pool_kernel<<<(NN + 127) / 128, 64>>>(ba);
    final_kernel<<<NG, 64>>>(Wl, bl, out);
}

// round 4
// speedup vs baseline: 1.5699x; 1.1842x over previous
#include <cuda_runtime.h>
#include <cuda_fp16.h>
#include <math.h>

#define NN 50000
#define NE 1200000
#define NG 128
#define NBLK 49            // ceil(NN/1024)
#define EPSF 1e-7f
#define MAXNORM (1.0f - 1e-5f)
#define ACLAMP 6.1030338f  // arctanh(1 - 1e-5)

// ---------------- scratch (static device globals; no allocation) -------------
__device__ int     g_flagE;
__device__ int     g_flagB;
__device__ int     g_deg[NN];
__device__ int     g_off[NN];
__device__ int     g_cur[NN];
__device__ int     g_adj[NE];
__device__ int     g_bsum[64];
__device__ int     g_bbase[64];
__device__ int     g_gstart[NG + 1];
__device__ float   g_pool[NG * 64];
__device__ __half2 g_th2[NN * 32];   // node features fp16 (stride 16 or 32 half2)
__device__ float   g_agg[NN * 64];

#define G_TH ((__half*)g_th2)

__device__ __forceinline__ int load_idx(const void* p, int i, int flag64) {
    return flag64 ? (int)((const long long*)p)[i] : ((const int*)p)[i];
}

// ---------------- zero + dtype detection (block 0) ---------------------------
// int64-vs-int32 sniffer: odd 32-bit words of small int64 values are all zero.
// Windows are mid-array so the sorted batch head (all zeros) can't fool it.
__global__ void zero_kernel(const int* __restrict__ ei, const int* __restrict__ ba) {
    int i = blockIdx.x * blockDim.x + threadIdx.x;
    if (i < NN)      g_deg[i]  = 0;
    if (i < NG * 64) g_pool[i] = 0.0f;
    if (blockIdx.x == 0) {
        __shared__ int nzE, nzB;
        if (threadIdx.x == 0) { nzE = 0; nzB = 0; }
        __syncthreads();
        for (int w = NE + 1 + 2 * threadIdx.x; w < NE + 2048; w += 2 * blockDim.x)
            if (ei[w] != 0) atomicOr(&nzE, 1);
        for (int w = 48001 + 2 * threadIdx.x; w < 50000; w += 2 * blockDim.x)
            if (ba[w] != 0) atomicOr(&nzB, 1);
        __syncthreads();
        if (threadIdx.x == 0) { g_flagE = (nzE == 0); g_flagB = (nzB == 0); }
    }
}

__global__ void deg_kernel(const void* __restrict__ ei) {
    int e = blockIdx.x * blockDim.x + threadIdx.x;
    if (e >= NE) return;
    int dst = load_idx(ei, NE + e, g_flagE);
    atomicAdd(&g_deg[dst], 1);
}

// ---- 3-phase exclusive scan of g_deg -> g_off/g_cur -------------------------
__global__ void scan1_kernel() {   // 49 blocks x 1024: per-block inclusive scan
    int i = blockIdx.x * 1024 + threadIdx.x;
    int lane = threadIdx.x & 31, wid = threadIdx.x >> 5;
    int v = (i < NN) ? g_deg[i] : 0;
    int s = v;
    #pragma unroll
    for (int o = 1; o < 32; o <<= 1) { int t = __shfl_up_sync(0xffffffffu, s, o); if (lane >= o) s += t; }
    __shared__ int wsum[32];
    if (lane == 31) wsum[wid] = s;
    __syncthreads();
    if (wid == 0) {
        int t = wsum[lane];
        #pragma unroll
        for (int o = 1; o < 32; o <<= 1) { int u = __shfl_up_sync(0xffffffffu, t, o); if (lane >= o) t += u; }
        wsum[lane] = t;
    }
    __syncthreads();
    int incl = s + (wid ? wsum[wid - 1] : 0);
    if (i < NN) g_off[i] = incl;
    if (threadIdx.x == 1023) g_bsum[blockIdx.x] = incl;
}

__global__ void scan2_kernel() {   // scan the 49 block totals
    __shared__ int sh[64];
    int t = threadIdx.x;
    int v = (t < NBLK) ? g_bsum[t] : 0;
    sh[t] = v;
    __syncthreads();
    for (int o = 1; o < 64; o <<= 1) {
        int u = (t >= o) ? sh[t - o] : 0;
        __syncthreads();
        sh[t] += u;
        __syncthreads();
    }
    g_bbase[t] = sh[t] - v;        // exclusive
}

// to-exclusive + block base; ALSO: graph boundary detection on sorted batch
__global__ void scan3_kernel(const void* __restrict__ ba) {
    int i = blockIdx.x * blockDim.x + threadIdx.x;
    if (i >= NN) return;
    int e = g_off[i] - g_deg[i] + g_bbase[i >> 10];
    g_off[i] = e;
    g_cur[i] = e;
    int f = g_flagB;
    int b  = load_idx(ba, i, f);
    int bp = (i == 0) ? -1 : load_idx(ba, i - 1, f);
    for (int g = bp + 1; g <= b; g++) g_gstart[g] = i;
    if (i == NN - 1)
        for (int g = b + 1; g <= NG; g++) g_gstart[g] = NN;
}

__global__ void adj_kernel(const void* __restrict__ ei) {
    int e = blockIdx.x * blockDim.x + threadIdx.x;
    if (e >= NE) return;
    int f = g_flagE;
    int src = load_idx(ei, e, f);
    int dst = load_idx(ei, NE + e, f);
    int pos = atomicAdd(&g_cur[dst], 1);
    g_adj[pos] = src;
}

// t0 = norm-clamp(x), stored fp16 stride 32 halves
__global__ void t0_kernel(const float* __restrict__ x) {
    int gid = blockIdx.x * blockDim.x + threadIdx.x;
    int node = gid >> 5, lane = gid & 31;
    if (node >= NN) return;
    float v = x[node * 32 + lane];
    float ss = v * v;
    #pragma unroll
    for (int o = 16; o; o >>= 1) ss += __shfl_xor_sync(0xffffffffu, ss, o);
    float nrm = sqrtf(ss);
    float s = (nrm > ACLAMP) ? (ACLAMP / nrm) : 1.0f;
    G_TH[node * 32 + lane] = __float2half_rn(v * s);
}

// ------- mean aggregation: 32-d path, HALF-WARP (16 lanes x half2) per node --
__global__ void agg32_kernel() {
    int gid = blockIdx.x * blockDim.x + threadIdx.x;
    int node = gid >> 4, lane = gid & 15;
    if (node >= NN) return;
    const __half2* __restrict__ tin = g_th2;   // 16 half2 per node
    int o = g_off[node];
    int d = g_deg[node];
    float ax = 0.0f, ay = 0.0f, bx = 0.0f, by = 0.0f;
    int j = 0;
    for (; j + 8 <= d; j += 8) {
        int s0 = g_adj[o + j],     s1 = g_adj[o + j + 1];
        int s2 = g_adj[o + j + 2], s3 = g_adj[o + j + 3];
        int s4 = g_adj[o + j + 4], s5 = g_adj[o + j + 5];
        int s6 = g_adj[o + j + 6], s7 = g_adj[o + j + 7];
        float2 v0 = __half22float2(tin[s0 * 16 + lane]);
        float2 v1 = __half22float2(tin[s1 * 16 + lane]);
        float2 v2 = __half22float2(tin[s2 * 16 + lane]);
        float2 v3 = __half22float2(tin[s3 * 16 + lane]);
        float2 v4 = __half22float2(tin[s4 * 16 + lane]);
        float2 v5 = __half22float2(tin[s5 * 16 + lane]);
        float2 v6 = __half22float2(tin[s6 * 16 + lane]);
        float2 v7 = __half22float2(tin[s7 * 16 + lane]);
        ax += (v0.x + v1.x) + (v2.x + v3.x);
        ay += (v0.y + v1.y) + (v2.y + v3.y);
        bx += (v4.x + v5.x) + (v6.x + v7.x);
        by += (v4.y + v5.y) + (v6.y + v7.y);
    }
    for (; j < d; j++) {
        float2 v = __half22float2(tin[g_adj[o + j] * 16 + lane]);
        ax += v.x; ay += v.y;
    }
    float inv = 1.0f / (float)((d > 0) ? d : 1);
    float2 r;
    r.x = (ax + bx) * inv;
    r.y = (ay + by) * inv;
    ((float2*)g_agg)[node * 16 + lane] = r;
}

// ------- mean aggregation: 64-d path, warp (32 lanes x half2) per node -------
__global__ void agg64_kernel() {
    int gid = blockIdx.x * blockDim.x + threadIdx.x;
    int node = gid >> 5, lane = gid & 31;
    if (node >= NN) return;
    const __half2* __restrict__ tin = g_th2;   // 32 half2 per node
    int o = g_off[node];
    int d = g_deg[node];
    float ax = 0.0f, ay = 0.0f, bx = 0.0f, by = 0.0f;
    int j = 0;
    for (; j + 8 <= d; j += 8) {
        int s0 = g_adj[o + j],     s1 = g_adj[o + j + 1];
        int s2 = g_adj[o + j + 2], s3 = g_adj[o + j + 3];
        int s4 = g_adj[o + j + 4], s5 = g_adj[o + j + 5];
        int s6 = g_adj[o + j + 6], s7 = g_adj[o + j + 7];
        float2 v0 = __half22float2(tin[s0 * 32 + lane]);
        float2 v1 = __half22float2(tin[s1 * 32 + lane]);
        float2 v2 = __half22float2(tin[s2 * 32 + lane]);
        float2 v3 = __half22float2(tin[s3 * 32 + lane]);
        float2 v4 = __half22float2(tin[s4 * 32 + lane]);
        float2 v5 = __half22float2(tin[s5 * 32 + lane]);
        float2 v6 = __half22float2(tin[s6 * 32 + lane]);
        float2 v7 = __half22float2(tin[s7 * 32 + lane]);
        ax += (v0.x + v1.x) + (v2.x + v3.x);
        ay += (v0.y + v1.y) + (v2.y + v3.y);
        bx += (v4.x + v5.x) + (v6.x + v7.x);
        by += (v4.y + v5.y) + (v6.y + v7.y);
    }
    for (; j < d; j++) {
        float2 v = __half22float2(tin[g_adj[o + j] * 32 + lane]);
        ax += v.x; ay += v.y;
    }
    float inv = 1.0f / (float)((d > 0) ? d : 1);
    float2 r;
    r.x = (ax + bx) * inv;
    r.y = (ay + by) * inv;
    ((float2*)g_agg)[node * 32 + lane] = r;
}

// ---------- GEMM (agg @ W + b) + act + norm-clamp + deg==0 zeroing -----------
template <int DIMIN, int ACT>
__global__ __launch_bounds__(256) void gemm_kernel(const float* __restrict__ W,
                                                   const float* __restrict__ b) {
    __shared__ float As[64 * 65];
    __shared__ __align__(16) float Ws[64 * 64];
    __shared__ float ssc[64];
    int tid = threadIdx.x;
    int row0 = blockIdx.x * 64;

    for (int idx = tid; idx < 64 * DIMIN; idx += 256) {
        int r = idx / DIMIN, c = idx % DIMIN;
        int row = row0 + r;
        As[r * 65 + c] = (row < NN) ? g_agg[row * DIMIN + c] : 0.0f;
    }
    for (int idx = tid; idx < DIMIN * 64; idx += 256) Ws[idx] = W[idx];
    __syncthreads();

    int rb = (tid >> 4) * 4, cb = (tid & 15) * 4;
    float acc[4][4];
    #pragma unroll
    for (int i = 0; i < 4; i++)
        #pragma unroll
        for (int j = 0; j < 4; j++) acc[i][j] = b[cb + j];

    #pragma unroll 8
    for (int k = 0; k < DIMIN; k++) {
        float a0 = As[(rb + 0) * 65 + k];
        float a1 = As[(rb + 1) * 65 + k];
        float a2 = As[(rb + 2) * 65 + k];
        float a3 = As[(rb + 3) * 65 + k];
        float4 w = *(const float4*)&Ws[k * 64 + cb];
        acc[0][0] += a0 * w.x; acc[0][1] += a0 * w.y; acc[0][2] += a0 * w.z; acc[0][3] += a0 * w.w;
        acc[1][0] += a1 * w.x; acc[1][1] += a1 * w.y; acc[1][2] += a1 * w.z; acc[1][3] += a1 * w.w;
        acc[2][0] += a2 * w.x; acc[2][1] += a2 * w.y; acc[2][2] += a2 * w.z; acc[2][3] += a2 * w.w;
        acc[3][0] += a3 * w.x; acc[3][1] += a3 * w.y; acc[3][2] += a3 * w.z; acc[3][3] += a3 * w.w;
    }
    __syncthreads();

    #pragma unroll
    for (int i = 0; i < 4; i++)
        #pragma unroll
        for (int j = 0; j < 4; j++) {
            float u = acc[i][j];
            if (ACT) u = (u > 0.0f) ? u : 0.2f * u;
            As[(rb + i) * 65 + (cb + j)] = u;
        }
    __syncthreads();

    if (tid < 64) {
        float ss = 0.0f;
        #pragma unroll 8
        for (int c = 0; c < 64; c++) { float u = As[tid * 65 + c]; ss += u * u; }
        float nrm = sqrtf(ss);
        float s = (nrm > ACLAMP) ? (ACLAMP / nrm) : 1.0f;
        int row = row0 + tid;
        if (row < NN && g_deg[row] == 0) s = 0.0f;
        ssc[tid] = s;
    }
    __syncthreads();

    for (int idx = tid; idx < 64 * 64; idx += 256) {
        int r = idx >> 6, c = idx & 63;
        int row = row0 + r;
        if (row < NN) G_TH[row * 64 + c] = __float2half_rn(As[r * 65 + c] * ssc[r]);
    }
}

// ------- graph pooling: 4 independent 32-node run-length subranges / block ---
__global__ void pool_kernel(const void* __restrict__ ba) {
    int c = threadIdx.x & 63;              // column 0..63
    int q = threadIdx.x >> 6;              // subrange 0..3
    int n0 = blockIdx.x * 128 + q * 32;
    int n1 = min(n0 + 32, NN);
    if (n0 >= NN) return;
    int f = g_flagB;
    int gprev = load_idx(ba, n0, f);
    float acc = 0.0f;
    for (int n = n0; n < n1; n++) {
        int g = load_idx(ba, n, f);
        if (g != gprev) {
            atomicAdd(&g_pool[gprev * 64 + c], acc);
            acc = 0.0f;
            gprev = g;
        }
        acc += __half2float(G_TH[n * 64 + c]);
    }
    atomicAdd(&g_pool[gprev * 64 + c], acc);
}

// ---------------- head: mean-pool -> clamp -> linear -> expmap0 -> proj ------
__global__ void final_kernel(const float* __restrict__ Wl,
                             const float* __restrict__ bl,
                             float* __restrict__ out) {
    __shared__ float sht[64];
    __shared__ float shz[10];
    __shared__ float shred[2];
    __shared__ float shF;
    int g = blockIdx.x, c = threadIdx.x;
    float cnt = (float)max(g_gstart[g + 1] - g_gstart[g], 1);
    float v = g_pool[g * 64 + c] / cnt;
    float ss = v * v;
    #pragma unroll
    for (int o = 16; o; o >>= 1) ss += __shfl_xor_sync(0xffffffffu, ss, o);
    if ((c & 31) == 0) shred[c >> 5] = ss;
    __syncthreads();
    float nrm = sqrtf(shred[0] + shred[1]);
    float s = (nrm > ACLAMP) ? (ACLAMP / nrm) : 1.0f;
    sht[c] = v * s;
    __syncthreads();
    if (c < 10) {
        float z = bl[c];
        #pragma unroll 8
        for (int k = 0; k < 64; k++) z += sht[k] * Wl[k * 10 + c];
        shz[c] = z;
    }
    __syncthreads();
    if (c == 0) {
        float s2 = 0.0f;
        #pragma unroll
        for (int j = 0; j < 10; j++) s2 += shz[j] * shz[j];
        float n2 = sqrtf(s2);
        float nn = fmaxf(n2, EPSF);
        float fac = tanhf(nn) / nn;
        float ny = fac * n2;
        float F = fac;
        if (ny > MAXNORM) F = fac * (MAXNORM / fmaxf(ny, EPSF));
        shF = F;
    }
    __syncthreads();
    if (c < 10) out[g * 10 + c] = shz[c] * shF;
}

// ---------------- launch ------------------------------------------------------
extern "C" void kernel_launch(void* const* d_in, const int* in_sizes, int n_in,
                              void* d_out, int out_size) {
    const float* x  = (const float*)d_in[0];
    const void*  ei = d_in[1];
    const void*  ba = d_in[2];
    const float* W1 = (const float*)d_in[3];
    const float* b1 = (const float*)d_in[4];
    const float* W2 = (const float*)d_in[5];
    const float* b2 = (const float*)d_in[6];
    const float* W3 = (const float*)d_in[7];
    const float* b3 = (const float*)d_in[8];
    const float* Wl = (const float*)d_in[9];
    const float* bl = (const float*)d_in[10];
    float* out = (float*)d_out;

    zero_kernel<<<(NN + 255) / 256, 256>>>((const int*)ei, (const int*)ba);
    deg_kernel<<<(NE + 255) / 256, 256>>>(ei);
    scan1_kernel<<<NBLK, 1024>>>();
    scan2_kernel<<<1, 64>>>();
    scan3_kernel<<<(NN + 255) / 256, 256>>>(ba);
    adj_kernel<<<(NE + 255) / 256, 256>>>(ei);

    t0_kernel<<<(NN * 32 + 255) / 256, 256>>>(x);

    const int GEMM_GRID = (NN + 63) / 64;

    agg32_kernel<<<(NN * 16 + 255) / 256, 256>>>();
    gemm_kernel<32, 1><<<GEMM_GRID, 256>>>(W1, b1);
    agg64_kernel<<<(NN * 32 + 255) / 256, 256>>>();
    gemm_kernel<64, 1><<<GEMM_GRID, 256>>>(W2, b2);
    agg64_kernel<<<(NN * 32 + 255) / 256, 256>>>();
    gemm_kernel<64, 0><<<GEMM_GRID, 256>>>(W3, b3);

    pool_kernel<<<(NN + 127) / 128, 256>>>(ba);
    final_kernel<<<NG, 64>>>(Wl, bl, out);
}